// round 2
// baseline (speedup 1.0000x reference)
#include <cuda_runtime.h>

#define NN 50000
#define NE 800000
#define EE (NE + NN)          // edges + self loops
#define H  6
#define C  32
#define D  192
#define NEG_SLOPE 0.2f

// ---------------- static scratch (no allocations allowed) ----------------
__device__ float g_XL[NN * D];        // x @ W_l^T + b_l
__device__ float g_XR[NN * D];        // x @ W_r^T + b_r
__device__ float g_SC[(size_t)EE * H];// per-edge score, then exp()
__device__ float g_SMAX[NN * H];      // segment max
__device__ float g_DEN[NN * H];       // segment sum of exp

// ---------------- GEMM: out[n][d] = sum_k X[n][k]*W[d][k] + b[d] ----------
// block = 192 threads (one per output column), 32 rows per block.
__global__ void gemm_kernel(const float* __restrict__ X,
                            const float* __restrict__ W,
                            const float* __restrict__ b,
                            float* __restrict__ out) {
    __shared__ float xs[32][D];
    const int row0 = blockIdx.x * 32;
    const int d = threadIdx.x;           // 0..191

    // cooperative load of 32 rows of X
    for (int i = threadIdx.x; i < 32 * D; i += D) {
        int r = i / D, c = i % D;
        int row = row0 + r;
        xs[r][c] = (row < NN) ? X[(size_t)row * D + c] : 0.f;
    }
    __syncthreads();

    float acc[32];
#pragma unroll
    for (int r = 0; r < 32; r++) acc[r] = 0.f;

    const float4* W4 = reinterpret_cast<const float4*>(W + (size_t)d * D);
    for (int k4 = 0; k4 < D / 4; k4++) {
        float4 w = W4[k4];
#pragma unroll
        for (int r = 0; r < 32; r++) {
            float4 xv = *reinterpret_cast<const float4*>(&xs[r][k4 * 4]);
            acc[r] += xv.x * w.x + xv.y * w.y + xv.z * w.z + xv.w * w.w;
        }
    }
    const float bb = b[d];
#pragma unroll
    for (int r = 0; r < 32; r++) {
        int row = row0 + r;
        if (row < NN) out[(size_t)row * D + d] = acc[r] + bb;
    }
}

// ---------------- init: SMAX=-inf, DEN=0, out=0 ---------------------------
__global__ void init_kernel(float* __restrict__ out) {
    int i = blockIdx.x * blockDim.x + threadIdx.x;
    if (i < NN * H) { g_SMAX[i] = -INFINITY; g_DEN[i] = 0.f; }
    if (i < NN * D) out[i] = 0.f;
}

// ---------------- float atomic max (order-preserving int trick) -----------
__device__ __forceinline__ void atomicMaxFloat(float* addr, float v) {
    if (v >= 0.f) atomicMax((int*)addr, __float_as_int(v));
    else          atomicMin((unsigned int*)addr, __float_as_uint(v));
}

// ---------------- per-edge score + segment max ----------------------------
// one warp per edge; lane = channel c, unrolled over heads
__global__ void score_kernel(const int* __restrict__ ei,
                             const float* __restrict__ att) {
    int gw = (blockIdx.x * blockDim.x + threadIdx.x) >> 5;
    int lane = threadIdx.x & 31;
    if (gw >= EE) return;
    int src, dst;
    if (gw < NE) { src = ei[gw]; dst = ei[NE + gw]; }
    else         { src = dst = gw - NE; }

    const float* xl = g_XL + (size_t)src * D;
    const float* xr = g_XR + (size_t)dst * D;

    float s[H];
#pragma unroll
    for (int h = 0; h < H; h++) {
        float m = xl[h * 32 + lane] + xr[h * 32 + lane];
        float v = (m > 0.f) ? m : NEG_SLOPE * m;
        s[h] = v * att[h * 32 + lane];
    }
#pragma unroll
    for (int h = 0; h < H; h++) {
#pragma unroll
        for (int off = 16; off; off >>= 1)
            s[h] += __shfl_xor_sync(0xffffffff, s[h], off);
    }
    if (lane == 0) {
        float* sc = g_SC + (size_t)gw * H;
        float* sm = g_SMAX + (size_t)dst * H;
#pragma unroll
        for (int h = 0; h < H; h++) {
            sc[h] = s[h];
            atomicMaxFloat(&sm[h], s[h]);
        }
    }
}

// ---------------- exp + segment sum ---------------------------------------
__global__ void exp_kernel(const int* __restrict__ ei) {
    long long i = (long long)blockIdx.x * blockDim.x + threadIdx.x;
    if (i >= (long long)EE * H) return;
    int e = (int)(i / H);
    int h = (int)(i - (long long)e * H);
    int dst = (e < NE) ? ei[NE + e] : e - NE;
    float ex = __expf(g_SC[i] - g_SMAX[dst * H + h]);
    g_SC[i] = ex;
    atomicAdd(&g_DEN[dst * H + h], ex);
}

// ---------------- weighted aggregation ------------------------------------
// one warp per edge; atomicAdd into out[dst]
__global__ void agg_kernel(const int* __restrict__ ei,
                           float* __restrict__ out) {
    int gw = (blockIdx.x * blockDim.x + threadIdx.x) >> 5;
    int lane = threadIdx.x & 31;
    if (gw >= EE) return;
    int src, dst;
    if (gw < NE) { src = ei[gw]; dst = ei[NE + gw]; }
    else         { src = dst = gw - NE; }

    const float* xl = g_XL + (size_t)src * D;
    const float* sc = g_SC + (size_t)gw * H;
    const float* dn = g_DEN + (size_t)dst * H;
    float* o = out + (size_t)dst * D;
#pragma unroll
    for (int h = 0; h < H; h++) {
        float alpha = sc[h] / (dn[h] + 1e-16f);
        atomicAdd(&o[h * 32 + lane], alpha * xl[h * 32 + lane]);
    }
}

// ---------------- epilogue: relu(x + agg + bias) --------------------------
__global__ void final_kernel(const float* __restrict__ x,
                             const float* __restrict__ bias,
                             float* __restrict__ out) {
    int i = blockIdx.x * blockDim.x + threadIdx.x;
    if (i >= NN * D) return;
    float v = x[i] + out[i] + bias[i % D];
    out[i] = fmaxf(v, 0.f);
}

// ---------------- launch --------------------------------------------------
extern "C" void kernel_launch(void* const* d_in, const int* in_sizes, int n_in,
                              void* d_out, int out_size) {
    const float* x    = (const float*)d_in[0];
    const float* W_l  = (const float*)d_in[1];
    const float* b_l  = (const float*)d_in[2];
    const float* W_r  = (const float*)d_in[3];
    const float* b_r  = (const float*)d_in[4];
    const float* att  = (const float*)d_in[5];
    const float* bias = (const float*)d_in[6];
    const int*   ei   = (const int*)d_in[7];   // int64 in reference, delivered as int32
    float* out = (float*)d_out;

    float* XL; cudaGetSymbolAddress((void**)&XL, g_XL);
    float* XR; cudaGetSymbolAddress((void**)&XR, g_XR);

    int gemm_blocks = (NN + 31) / 32;
    gemm_kernel<<<gemm_blocks, D>>>(x, W_l, b_l, XL);
    gemm_kernel<<<gemm_blocks, D>>>(x, W_r, b_r, XR);

    init_kernel<<<(NN * D + 255) / 256, 256>>>(out);

    int ew_blocks = (EE * 32 + 255) / 256;              // warp per edge
    score_kernel<<<ew_blocks, 256>>>(ei, att);

    long long ne = (long long)EE * H;
    exp_kernel<<<(int)((ne + 255) / 256), 256>>>(ei);

    agg_kernel<<<ew_blocks, 256>>>(ei, out);

    final_kernel<<<(NN * D + 255) / 256, 256>>>(x, bias, out);
}

// round 4
// speedup vs baseline: 1.4444x; 1.4444x over previous
#include <cuda_runtime.h>

#define NN 50000
#define NE 800000
#define EE (NE + NN)
#define H  6
#define C  32
#define D  192
#define NEG_SLOPE 0.2f

#define SCAN_B 512
#define NBLK ((NN + SCAN_B - 1) / SCAN_B)   // 98

// ---------------- static scratch ----------------
__device__ float g_XL[NN * D];   // x @ W_l^T + b_l
__device__ float g_XR[NN * D];   // x @ W_r^T + b_r
__device__ int   g_CNT[NN];      // in-degree (excl self loop)
__device__ int   g_ROW[NN];      // exclusive rowptr
__device__ int   g_CUR[NN];      // scatter cursor
__device__ int   g_BT[NBLK];     // scan block totals
__device__ int   g_ESRC[NE];     // CSR: src ids grouped by dst

// ---------------- GEMM: out[n][d] = sum_k X[n][k]*W[d][k] + b[d] ----------
__global__ void gemm_kernel(const float* __restrict__ X,
                            const float* __restrict__ W,
                            const float* __restrict__ b,
                            float* __restrict__ out) {
    __shared__ float xs[32][D];
    const int row0 = blockIdx.x * 32;
    const int d = threadIdx.x;           // 0..191

    for (int i = threadIdx.x; i < 32 * D; i += D) {
        int r = i / D, c = i % D;
        int row = row0 + r;
        xs[r][c] = (row < NN) ? X[(size_t)row * D + c] : 0.f;
    }
    __syncthreads();

    float acc[32];
#pragma unroll
    for (int r = 0; r < 32; r++) acc[r] = 0.f;

    const float4* W4 = reinterpret_cast<const float4*>(W + (size_t)d * D);
    for (int k4 = 0; k4 < D / 4; k4++) {
        float4 w = W4[k4];
#pragma unroll
        for (int r = 0; r < 32; r++) {
            float4 xv = *reinterpret_cast<const float4*>(&xs[r][k4 * 4]);
            acc[r] += xv.x * w.x + xv.y * w.y + xv.z * w.z + xv.w * w.w;
        }
    }
    const float bb = b[d];
#pragma unroll
    for (int r = 0; r < 32; r++) {
        int row = row0 + r;
        if (row < NN) out[(size_t)row * D + d] = acc[r] + bb;
    }
}

// ---------------- CSR build ----------------
__global__ void zero_cnt_kernel() {
    int i = blockIdx.x * blockDim.x + threadIdx.x;
    if (i < NN) g_CNT[i] = 0;
}

__global__ void hist_kernel(const int* __restrict__ ei) {
    int e = blockIdx.x * blockDim.x + threadIdx.x;
    if (e < NE) atomicAdd(&g_CNT[ei[NE + e]], 1);
}

__global__ void scan1_kernel() {
    __shared__ int s[SCAN_B];
    int i = blockIdx.x * SCAN_B + threadIdx.x;
    int v = (i < NN) ? g_CNT[i] : 0;
    s[threadIdx.x] = v;
    __syncthreads();
    for (int off = 1; off < SCAN_B; off <<= 1) {
        int t = (threadIdx.x >= off) ? s[threadIdx.x - off] : 0;
        __syncthreads();
        s[threadIdx.x] += t;
        __syncthreads();
    }
    if (i < NN) g_ROW[i] = s[threadIdx.x] - v;   // exclusive within block
    if (threadIdx.x == SCAN_B - 1) g_BT[blockIdx.x] = s[threadIdx.x];
}

__global__ void scan2_kernel() {
    if (threadIdx.x == 0) {
        int acc = 0;
        for (int b = 0; b < NBLK; b++) { int t = g_BT[b]; g_BT[b] = acc; acc += t; }
    }
}

__global__ void scan3_kernel() {
    int i = blockIdx.x * blockDim.x + threadIdx.x;
    if (i < NN) {
        int r = g_ROW[i] + g_BT[i / SCAN_B];
        g_ROW[i] = r;
        g_CUR[i] = r;
    }
}

__global__ void scatter_kernel(const int* __restrict__ ei) {
    int e = blockIdx.x * blockDim.x + threadIdx.x;
    if (e < NE) {
        int dst = ei[NE + e];
        int pos = atomicAdd(&g_CUR[dst], 1);
        g_ESRC[pos] = ei[e];
    }
}

// ---------------- warp-wide float add reduction (butterfly shfl) ----------
__device__ __forceinline__ float warp_sum(float v) {
#pragma unroll
    for (int off = 16; off; off >>= 1)
        v += __shfl_xor_sync(0xffffffff, v, off);
    return v;
}

// ---------------- fused GATv2: score + online softmax + agg + epilogue ----
// one warp per dst node; lane = channel within head
__global__ void fused_kernel(const float* __restrict__ x,
                             const float* __restrict__ att,
                             const float* __restrict__ bias,
                             float* __restrict__ out) {
    int dst = (blockIdx.x * blockDim.x + threadIdx.x) >> 5;
    int lane = threadIdx.x & 31;
    if (dst >= NN) return;

    float xr[H], a[H];
    const float* xrp = g_XR + (size_t)dst * D;
#pragma unroll
    for (int h = 0; h < H; h++) {
        xr[h] = xrp[h * 32 + lane];
        a[h]  = att[h * 32 + lane];
    }

    // self-loop seeds the online softmax state
    float acc[H], mx[H], den[H];
    {
        const float* xlp = g_XL + (size_t)dst * D;
#pragma unroll
        for (int h = 0; h < H; h++) {
            float xl = xlp[h * 32 + lane];
            float m = xl + xr[h];
            float v = (m > 0.f) ? m : NEG_SLOPE * m;
            float s = warp_sum(v * a[h]);
            mx[h] = s;
            den[h] = 1.f;
            acc[h] = xl;
        }
    }

    int jb = g_ROW[dst];
    int je = jb + g_CNT[dst];
    for (int j = jb; j < je; j++) {
        int src = g_ESRC[j];
        const float* xlp = g_XL + (size_t)src * D;
        float xl[H], s[H];
#pragma unroll
        for (int h = 0; h < H; h++) {
            xl[h] = xlp[h * 32 + lane];
            float m = xl[h] + xr[h];
            float v = (m > 0.f) ? m : NEG_SLOPE * m;
            s[h] = warp_sum(v * a[h]);
        }
#pragma unroll
        for (int h = 0; h < H; h++) {
            if (s[h] > mx[h]) {
                float r = __expf(mx[h] - s[h]);
                acc[h] = acc[h] * r + xl[h];
                den[h] = den[h] * r + 1.f;
                mx[h] = s[h];
            } else {
                float e = __expf(s[h] - mx[h]);
                acc[h] += e * xl[h];
                den[h] += e;
            }
        }
    }

    const float* xp = x + (size_t)dst * D;
    float* op = out + (size_t)dst * D;
#pragma unroll
    for (int h = 0; h < H; h++) {
        float v = xp[h * 32 + lane] + acc[h] / (den[h] + 1e-16f) + bias[h * 32 + lane];
        op[h * 32 + lane] = fmaxf(v, 0.f);
    }
}

// ---------------- launch --------------------------------------------------
extern "C" void kernel_launch(void* const* d_in, const int* in_sizes, int n_in,
                              void* d_out, int out_size) {
    const float* x    = (const float*)d_in[0];
    const float* W_l  = (const float*)d_in[1];
    const float* b_l  = (const float*)d_in[2];
    const float* W_r  = (const float*)d_in[3];
    const float* b_r  = (const float*)d_in[4];
    const float* att  = (const float*)d_in[5];
    const float* bias = (const float*)d_in[6];
    const int*   ei   = (const int*)d_in[7];
    float* out = (float*)d_out;

    float* XL; cudaGetSymbolAddress((void**)&XL, g_XL);
    float* XR; cudaGetSymbolAddress((void**)&XR, g_XR);

    zero_cnt_kernel<<<(NN + 255) / 256, 256>>>();

    int gemm_blocks = (NN + 31) / 32;
    gemm_kernel<<<gemm_blocks, D>>>(x, W_l, b_l, XL);
    gemm_kernel<<<gemm_blocks, D>>>(x, W_r, b_r, XR);

    hist_kernel<<<(NE + 255) / 256, 256>>>(ei);
    scan1_kernel<<<NBLK, SCAN_B>>>();
    scan2_kernel<<<1, 32>>>();
    scan3_kernel<<<(NN + 255) / 256, 256>>>();
    scatter_kernel<<<(NE + 255) / 256, 256>>>(ei);

    fused_kernel<<<(NN * 32 + 255) / 256, 256>>>(x, att, bias, out);
}

// round 5
// speedup vs baseline: 2.1146x; 1.4640x over previous
#include <cuda_runtime.h>

#define NN 50000
#define NE 800000
#define H  6
#define C  32
#define D  192
#define NEG_SLOPE 0.2f

#define SCAN_B 512
#define NBLK ((NN + SCAN_B - 1) / SCAN_B)   // 98

// ---------------- static scratch ----------------
__device__ float g_XL[NN * D];   // x @ W_l^T + b_l
__device__ float g_XR[NN * D];   // x @ W_r^T + b_r
__device__ int   g_CNT[NN];      // in-degree (excl self loop)
__device__ int   g_ROW[NN];      // exclusive rowptr
__device__ int   g_CUR[NN];      // scatter cursor
__device__ int   g_BT[NBLK];     // scan block totals
__device__ int   g_ESRC[NE];     // CSR: src ids grouped by dst

// ---------------- packed f32x2 helpers (Blackwell FFMA2) ------------------
#define PACK2(o, lo, hi) asm("mov.b64 %0, {%1, %2};" : "=l"(o) : "f"(lo), "f"(hi))
#define UNPACK2(lo, hi, i) asm("mov.b64 {%0, %1}, %2;" : "=f"(lo), "=f"(hi) : "l"(i))
#define FMA2(d, a, b, c) asm("fma.rn.f32x2 %0, %1, %2, %3;" : "=l"(d) : "l"(a), "l"(b), "l"(c))

// ---------------- GEMM: out[n][d] = sum_k X[n][k]*W[d][k] + b[d] ----------
// BM=64 rows/block, 256 threads; thread (tx,ty): 8 rows x 6 cols register tile.
// cols: {tx*4 .. tx*4+3} and {128+tx*2, 128+tx*2+1}. Packed f32x2 FMA.
#define BM 64
__global__ __launch_bounds__(256) void gemm_kernel(const float* __restrict__ X,
                                                   const float* __restrict__ W,
                                                   const float* __restrict__ b,
                                                   float* __restrict__ out) {
    __shared__ float xs[BM][33];    // [row][k] row-major, pad 33
    __shared__ float ws[32][196];   // [k][d]   k-major, pad 196 (16B-aligned rows)
    const int tid = threadIdx.x;
    const int tx = tid & 31, ty = tid >> 5;   // ty 0..7
    const int row0 = blockIdx.x * BM;

    unsigned long long acc[8][3];
#pragma unroll
    for (int i = 0; i < 8; i++)
#pragma unroll
        for (int j = 0; j < 3; j++) acc[i][j] = 0ull;  // packed {0.f,0.f}

    for (int kt = 0; kt < 6; kt++) {
        const int k0 = kt * 32;
        // X tile 64x32 (coalesced: lane=k)
        {
            const int kk = tid & 31;
            for (int r = tid >> 5; r < BM; r += 8) {
                int row = row0 + r;
                xs[r][kk] = (row < NN) ? X[(size_t)row * D + k0 + kk] : 0.f;
            }
        }
        // W tile 192x32 -> ws[k][d] (coalesced: lane=k)
        {
            const int kk = tid & 31;
            for (int d = tid >> 5; d < D; d += 8)
                ws[kk][d] = W[(size_t)d * D + k0 + kk];
        }
        __syncthreads();
#pragma unroll
        for (int k = 0; k < 32; k++) {
            float2 wa = *(const float2*)&ws[k][tx * 4];
            float2 wb = *(const float2*)&ws[k][tx * 4 + 2];
            float2 wc = *(const float2*)&ws[k][128 + tx * 2];
            unsigned long long wA, wB, wC;
            PACK2(wA, wa.x, wa.y);
            PACK2(wB, wb.x, wb.y);
            PACK2(wC, wc.x, wc.y);
#pragma unroll
            for (int i = 0; i < 8; i++) {
                float xv = xs[ty * 8 + i][k];
                unsigned long long xp;
                PACK2(xp, xv, xv);
                FMA2(acc[i][0], xp, wA, acc[i][0]);
                FMA2(acc[i][1], xp, wB, acc[i][1]);
                FMA2(acc[i][2], xp, wC, acc[i][2]);
            }
        }
        __syncthreads();
    }

    float4 bb0 = *(const float4*)&b[tx * 4];
    float2 bb1 = *(const float2*)&b[128 + tx * 2];
#pragma unroll
    for (int i = 0; i < 8; i++) {
        int row = row0 + ty * 8 + i;
        if (row < NN) {
            float a0, a1, a2, a3, a4, a5;
            UNPACK2(a0, a1, acc[i][0]);
            UNPACK2(a2, a3, acc[i][1]);
            UNPACK2(a4, a5, acc[i][2]);
            float4 o0 = {a0 + bb0.x, a1 + bb0.y, a2 + bb0.z, a3 + bb0.w};
            *(float4*)&out[(size_t)row * D + tx * 4] = o0;
            float2 o1 = {a4 + bb1.x, a5 + bb1.y};
            *(float2*)&out[(size_t)row * D + 128 + tx * 2] = o1;
        }
    }
}

// ---------------- CSR build ----------------
__global__ void zero_cnt_kernel() {
    int i = blockIdx.x * blockDim.x + threadIdx.x;
    if (i < NN) g_CNT[i] = 0;
}

__global__ void hist_kernel(const int* __restrict__ ei) {
    int e = blockIdx.x * blockDim.x + threadIdx.x;
    if (e < NE) atomicAdd(&g_CNT[ei[NE + e]], 1);
}

__global__ void scan1_kernel() {
    __shared__ int s[SCAN_B];
    int i = blockIdx.x * SCAN_B + threadIdx.x;
    int v = (i < NN) ? g_CNT[i] : 0;
    s[threadIdx.x] = v;
    __syncthreads();
    for (int off = 1; off < SCAN_B; off <<= 1) {
        int t = (threadIdx.x >= off) ? s[threadIdx.x - off] : 0;
        __syncthreads();
        s[threadIdx.x] += t;
        __syncthreads();
    }
    if (i < NN) g_ROW[i] = s[threadIdx.x] - v;
    if (threadIdx.x == SCAN_B - 1) g_BT[blockIdx.x] = s[threadIdx.x];
}

__global__ void scan2_kernel() {
    if (threadIdx.x == 0) {
        int acc = 0;
        for (int b = 0; b < NBLK; b++) { int t = g_BT[b]; g_BT[b] = acc; acc += t; }
    }
}

__global__ void scan3_kernel() {
    int i = blockIdx.x * blockDim.x + threadIdx.x;
    if (i < NN) {
        int r = g_ROW[i] + g_BT[i / SCAN_B];
        g_ROW[i] = r;
        g_CUR[i] = r;
    }
}

__global__ void scatter_kernel(const int* __restrict__ ei) {
    int e = blockIdx.x * blockDim.x + threadIdx.x;
    if (e < NE) {
        int dst = ei[NE + e];
        int pos = atomicAdd(&g_CUR[dst], 1);
        g_ESRC[pos] = ei[e];
    }
}

// ---------------- warp-wide float add reduction (butterfly shfl) ----------
__device__ __forceinline__ float warp_sum(float v) {
#pragma unroll
    for (int off = 16; off; off >>= 1)
        v += __shfl_xor_sync(0xffffffff, v, off);
    return v;
}

// ---------------- fused GATv2: score + softmax + agg + epilogue -----------
// one warp per dst; plain exp (scores bounded ~|3|, shift-invariant softmax)
__global__ void fused_kernel(const float* __restrict__ x,
                             const float* __restrict__ att,
                             const float* __restrict__ bias,
                             float* __restrict__ out) {
    int dst = (blockIdx.x * blockDim.x + threadIdx.x) >> 5;
    int lane = threadIdx.x & 31;
    if (dst >= NN) return;

    float xr[H], a[H], acc[H], den[H];
    const float* xrp = g_XR + (size_t)dst * D;
#pragma unroll
    for (int h = 0; h < H; h++) {
        xr[h] = xrp[h * 32 + lane];
        a[h]  = att[h * 32 + lane];
    }

    // self-loop seed
    {
        const float* xlp = g_XL + (size_t)dst * D;
#pragma unroll
        for (int h = 0; h < H; h++) {
            float xl = xlp[h * 32 + lane];
            float m = xl + xr[h];
            float v = fmaxf(m, NEG_SLOPE * m);
            float e = __expf(warp_sum(v * a[h]));
            acc[h] = e * xl;
            den[h] = e;
        }
    }

    const int jb = g_ROW[dst];
    const int je = jb + g_CNT[dst];
    int j = jb;
    // unrolled by 2: two independent gather+butterfly chains in flight
    for (; j + 1 < je; j += 2) {
        int s0 = g_ESRC[j], s1 = g_ESRC[j + 1];
        const float* p0 = g_XL + (size_t)s0 * D;
        const float* p1 = g_XL + (size_t)s1 * D;
        float xl0[H], xl1[H], t0[H], t1[H];
#pragma unroll
        for (int h = 0; h < H; h++) {
            xl0[h] = p0[h * 32 + lane];
            xl1[h] = p1[h * 32 + lane];
            float m0 = xl0[h] + xr[h];
            float m1 = xl1[h] + xr[h];
            t0[h] = fmaxf(m0, NEG_SLOPE * m0) * a[h];
            t1[h] = fmaxf(m1, NEG_SLOPE * m1) * a[h];
        }
#pragma unroll
        for (int h = 0; h < H; h++) {
            float e0 = __expf(warp_sum(t0[h]));
            float e1 = __expf(warp_sum(t1[h]));
            acc[h] += e0 * xl0[h] + e1 * xl1[h];
            den[h] += e0 + e1;
        }
    }
    if (j < je) {
        int s0 = g_ESRC[j];
        const float* p0 = g_XL + (size_t)s0 * D;
#pragma unroll
        for (int h = 0; h < H; h++) {
            float xl = p0[h * 32 + lane];
            float m = xl + xr[h];
            float e = __expf(warp_sum(fmaxf(m, NEG_SLOPE * m) * a[h]));
            acc[h] += e * xl;
            den[h] += e;
        }
    }

    const float* xp = x + (size_t)dst * D;
    float* op = out + (size_t)dst * D;
#pragma unroll
    for (int h = 0; h < H; h++) {
        float v = xp[h * 32 + lane] + acc[h] / (den[h] + 1e-16f) + bias[h * 32 + lane];
        op[h * 32 + lane] = fmaxf(v, 0.f);
    }
}

// ---------------- launch --------------------------------------------------
extern "C" void kernel_launch(void* const* d_in, const int* in_sizes, int n_in,
                              void* d_out, int out_size) {
    const float* x    = (const float*)d_in[0];
    const float* W_l  = (const float*)d_in[1];
    const float* b_l  = (const float*)d_in[2];
    const float* W_r  = (const float*)d_in[3];
    const float* b_r  = (const float*)d_in[4];
    const float* att  = (const float*)d_in[5];
    const float* bias = (const float*)d_in[6];
    const int*   ei   = (const int*)d_in[7];
    float* out = (float*)d_out;

    float* XL; cudaGetSymbolAddress((void**)&XL, g_XL);
    float* XR; cudaGetSymbolAddress((void**)&XR, g_XR);

    zero_cnt_kernel<<<(NN + 255) / 256, 256>>>();

    int gemm_blocks = (NN + BM - 1) / BM;
    gemm_kernel<<<gemm_blocks, 256>>>(x, W_l, b_l, XL);
    gemm_kernel<<<gemm_blocks, 256>>>(x, W_r, b_r, XR);

    hist_kernel<<<(NE + 255) / 256, 256>>>(ei);
    scan1_kernel<<<NBLK, SCAN_B>>>();
    scan2_kernel<<<1, 32>>>();
    scan3_kernel<<<(NN + 255) / 256, 256>>>();
    scatter_kernel<<<(NE + 255) / 256, 256>>>(ei);

    fused_kernel<<<(NN * 32 + 255) / 256, 256>>>(x, att, bias, out);
}

// round 6
// speedup vs baseline: 2.1240x; 1.0044x over previous
#include <cuda_runtime.h>

#define NN 50000
#define NE 800000
#define H  6
#define C  32
#define D  192
#define NEG_SLOPE 0.2f
#define LOG2E 1.4426950408889634f

#define SCAN_B 512
#define NBLK ((NN + SCAN_B - 1) / SCAN_B)   // 98

// ---------------- static scratch ----------------
__device__ float g_XL[NN * D];   // x @ W_l^T + b_l
__device__ float g_XR[NN * D];   // x @ W_r^T + b_r
__device__ int   g_CNT[NN];      // in-degree (excl self loop)
__device__ int   g_ROW[NN];      // exclusive rowptr
__device__ int   g_CUR[NN];      // scatter cursor
__device__ int   g_BT[NBLK];     // scan block totals
__device__ int   g_ESRC[NE];     // CSR: src ids grouped by dst

// ---------------- packed f32x2 helpers (Blackwell FFMA2) ------------------
#define PACK2(o, lo, hi) asm("mov.b64 %0, {%1, %2};" : "=l"(o) : "f"(lo), "f"(hi))
#define UNPACK2(lo, hi, i) asm("mov.b64 {%0, %1}, %2;" : "=f"(lo), "=f"(hi) : "l"(i))
#define FMA2(d, a, b, c) asm("fma.rn.f32x2 %0, %1, %2, %3;" : "=l"(d) : "l"(a), "l"(b), "l"(c))

// ---------------- GEMM: out[n][d] = sum_k X[n][k]*W[d][k] + b[d] ----------
#define BM 64
__global__ __launch_bounds__(256) void gemm_kernel(const float* __restrict__ X,
                                                   const float* __restrict__ W,
                                                   const float* __restrict__ b,
                                                   float* __restrict__ out) {
    __shared__ float xs[BM][33];
    __shared__ float ws[32][196];
    const int tid = threadIdx.x;
    const int tx = tid & 31, ty = tid >> 5;
    const int row0 = blockIdx.x * BM;

    unsigned long long acc[8][3];
#pragma unroll
    for (int i = 0; i < 8; i++)
#pragma unroll
        for (int j = 0; j < 3; j++) acc[i][j] = 0ull;

    for (int kt = 0; kt < 6; kt++) {
        const int k0 = kt * 32;
        {
            const int kk = tid & 31;
            for (int r = tid >> 5; r < BM; r += 8) {
                int row = row0 + r;
                xs[r][kk] = (row < NN) ? X[(size_t)row * D + k0 + kk] : 0.f;
            }
        }
        {
            const int kk = tid & 31;
            for (int d = tid >> 5; d < D; d += 8)
                ws[kk][d] = W[(size_t)d * D + k0 + kk];
        }
        __syncthreads();
#pragma unroll
        for (int k = 0; k < 32; k++) {
            float2 wa = *(const float2*)&ws[k][tx * 4];
            float2 wb = *(const float2*)&ws[k][tx * 4 + 2];
            float2 wc = *(const float2*)&ws[k][128 + tx * 2];
            unsigned long long wA, wB, wC;
            PACK2(wA, wa.x, wa.y);
            PACK2(wB, wb.x, wb.y);
            PACK2(wC, wc.x, wc.y);
#pragma unroll
            for (int i = 0; i < 8; i++) {
                float xv = xs[ty * 8 + i][k];
                unsigned long long xp;
                PACK2(xp, xv, xv);
                FMA2(acc[i][0], xp, wA, acc[i][0]);
                FMA2(acc[i][1], xp, wB, acc[i][1]);
                FMA2(acc[i][2], xp, wC, acc[i][2]);
            }
        }
        __syncthreads();
    }

    float4 bb0 = *(const float4*)&b[tx * 4];
    float2 bb1 = *(const float2*)&b[128 + tx * 2];
#pragma unroll
    for (int i = 0; i < 8; i++) {
        int row = row0 + ty * 8 + i;
        if (row < NN) {
            float a0, a1, a2, a3, a4, a5;
            UNPACK2(a0, a1, acc[i][0]);
            UNPACK2(a2, a3, acc[i][1]);
            UNPACK2(a4, a5, acc[i][2]);
            float4 o0 = {a0 + bb0.x, a1 + bb0.y, a2 + bb0.z, a3 + bb0.w};
            *(float4*)&out[(size_t)row * D + tx * 4] = o0;
            float2 o1 = {a4 + bb1.x, a5 + bb1.y};
            *(float2*)&out[(size_t)row * D + 128 + tx * 2] = o1;
        }
    }
}

// ---------------- CSR build ----------------
__global__ void zero_cnt_kernel() {
    int i = blockIdx.x * blockDim.x + threadIdx.x;
    if (i < NN) g_CNT[i] = 0;
}

__global__ void hist_kernel(const int* __restrict__ ei) {
    int e = blockIdx.x * blockDim.x + threadIdx.x;
    if (e < NE) atomicAdd(&g_CNT[ei[NE + e]], 1);
}

__global__ void scan1_kernel() {
    __shared__ int s[SCAN_B];
    int i = blockIdx.x * SCAN_B + threadIdx.x;
    int v = (i < NN) ? g_CNT[i] : 0;
    s[threadIdx.x] = v;
    __syncthreads();
    for (int off = 1; off < SCAN_B; off <<= 1) {
        int t = (threadIdx.x >= off) ? s[threadIdx.x - off] : 0;
        __syncthreads();
        s[threadIdx.x] += t;
        __syncthreads();
    }
    if (i < NN) g_ROW[i] = s[threadIdx.x] - v;
    if (threadIdx.x == SCAN_B - 1) g_BT[blockIdx.x] = s[threadIdx.x];
}

__global__ void scan2_kernel() {
    if (threadIdx.x == 0) {
        int acc = 0;
        for (int b = 0; b < NBLK; b++) { int t = g_BT[b]; g_BT[b] = acc; acc += t; }
    }
}

__global__ void scan3_kernel() {
    int i = blockIdx.x * blockDim.x + threadIdx.x;
    if (i < NN) {
        int r = g_ROW[i] + g_BT[i / SCAN_B];
        g_ROW[i] = r;
        g_CUR[i] = r;
    }
}

__global__ void scatter_kernel(const int* __restrict__ ei) {
    int e = blockIdx.x * blockDim.x + threadIdx.x;
    if (e < NE) {
        int dst = ei[NE + e];
        int pos = atomicAdd(&g_CUR[dst], 1);
        g_ESRC[pos] = ei[e];
    }
}

// ---------------- fast exp2 ----------------
__device__ __forceinline__ float ex2(float v) {
    float r;
    asm("ex2.approx.f32 %0, %1;" : "=f"(r) : "f"(v));
    return r;
}

// ---------------- 6-head reduce + exp, cheap form ----------------
// in: t[h] = per-lane contribution (already scaled by log2e)
// out: e[h] = exp(sum over 32 lanes of t[h]), broadcast to all lanes
__device__ __forceinline__ void reduce6_exp(const float* t, float* e, int lane) {
    float u[H];
#pragma unroll
    for (int h = 0; h < H; h++) {
        float v = t[h];
        v += __shfl_xor_sync(0xffffffffu, v, 16);
        v += __shfl_xor_sync(0xffffffffu, v, 8);
        u[h] = v;   // 8 distinct partials per head, replicated x4
    }
    int g = lane >> 3;
    float v1 = (g == 0) ? u[0] : (g == 1) ? u[1] : (g == 2) ? u[2] : u[3];
    float v2 = ((g & 1) == 0) ? u[4] : u[5];
    v1 += __shfl_xor_sync(0xffffffffu, v1, 4);
    v1 += __shfl_xor_sync(0xffffffffu, v1, 2);
    v1 += __shfl_xor_sync(0xffffffffu, v1, 1);
    v2 += __shfl_xor_sync(0xffffffffu, v2, 4);
    v2 += __shfl_xor_sync(0xffffffffu, v2, 2);
    v2 += __shfl_xor_sync(0xffffffffu, v2, 1);
    float e1 = ex2(v1);          // head g
    float e2 = ex2(v2);          // head 4 + (g&1)
    e[0] = __shfl_sync(0xffffffffu, e1, 0);
    e[1] = __shfl_sync(0xffffffffu, e1, 8);
    e[2] = __shfl_sync(0xffffffffu, e1, 16);
    e[3] = __shfl_sync(0xffffffffu, e1, 24);
    e[4] = __shfl_sync(0xffffffffu, e2, 0);
    e[5] = __shfl_sync(0xffffffffu, e2, 8);
}

// ---------------- fused GATv2: score + softmax + agg + epilogue -----------
// one warp per dst; plain exp (scores bounded, softmax shift-invariant)
__global__ void fused_kernel(const float* __restrict__ x,
                             const float* __restrict__ att,
                             const float* __restrict__ bias,
                             float* __restrict__ out) {
    int dst = (blockIdx.x * blockDim.x + threadIdx.x) >> 5;
    int lane = threadIdx.x & 31;
    if (dst >= NN) return;

    float xr[H], a[H], acc[H], den[H];
    const float* xrp = g_XR + (size_t)dst * D;
#pragma unroll
    for (int h = 0; h < H; h++) {
        xr[h] = xrp[h * 32 + lane];
        a[h]  = att[h * 32 + lane] * LOG2E;   // fold log2e: exp(s)=exp2(s*log2e)
    }

    // self-loop seed
    {
        const float* xlp = g_XL + (size_t)dst * D;
        float xl[H], t[H], e[H];
#pragma unroll
        for (int h = 0; h < H; h++) {
            xl[h] = xlp[h * 32 + lane];
            float m = xl[h] + xr[h];
            t[h] = fmaxf(m, NEG_SLOPE * m) * a[h];
        }
        reduce6_exp(t, e, lane);
#pragma unroll
        for (int h = 0; h < H; h++) {
            acc[h] = e[h] * xl[h];
            den[h] = e[h];
        }
    }

    const int jb = g_ROW[dst];
    const int je = jb + g_CNT[dst];
    int j = jb;
    for (; j + 1 < je; j += 2) {
        int s0 = g_ESRC[j], s1 = g_ESRC[j + 1];
        const float* p0 = g_XL + (size_t)s0 * D;
        const float* p1 = g_XL + (size_t)s1 * D;
        float xl0[H], xl1[H], t0[H], t1[H], e0[H], e1[H];
#pragma unroll
        for (int h = 0; h < H; h++) {
            xl0[h] = p0[h * 32 + lane];
            xl1[h] = p1[h * 32 + lane];
            float m0 = xl0[h] + xr[h];
            float m1 = xl1[h] + xr[h];
            t0[h] = fmaxf(m0, NEG_SLOPE * m0) * a[h];
            t1[h] = fmaxf(m1, NEG_SLOPE * m1) * a[h];
        }
        reduce6_exp(t0, e0, lane);
        reduce6_exp(t1, e1, lane);
#pragma unroll
        for (int h = 0; h < H; h++) {
            acc[h] += e0[h] * xl0[h] + e1[h] * xl1[h];
            den[h] += e0[h] + e1[h];
        }
    }
    if (j < je) {
        int s0 = g_ESRC[j];
        const float* p0 = g_XL + (size_t)s0 * D;
        float xl[H], t[H], e[H];
#pragma unroll
        for (int h = 0; h < H; h++) {
            xl[h] = p0[h * 32 + lane];
            float m = xl[h] + xr[h];
            t[h] = fmaxf(m, NEG_SLOPE * m) * a[h];
        }
        reduce6_exp(t, e, lane);
#pragma unroll
        for (int h = 0; h < H; h++) {
            acc[h] += e[h] * xl[h];
            den[h] += e[h];
        }
    }

    const float* xp = x + (size_t)dst * D;
    float* op = out + (size_t)dst * D;
#pragma unroll
    for (int h = 0; h < H; h++) {
        float v = xp[h * 32 + lane] + acc[h] / (den[h] + 1e-16f) + bias[h * 32 + lane];
        op[h * 32 + lane] = fmaxf(v, 0.f);
    }
}

// ---------------- launch --------------------------------------------------
extern "C" void kernel_launch(void* const* d_in, const int* in_sizes, int n_in,
                              void* d_out, int out_size) {
    const float* x    = (const float*)d_in[0];
    const float* W_l  = (const float*)d_in[1];
    const float* b_l  = (const float*)d_in[2];
    const float* W_r  = (const float*)d_in[3];
    const float* b_r  = (const float*)d_in[4];
    const float* att  = (const float*)d_in[5];
    const float* bias = (const float*)d_in[6];
    const int*   ei   = (const int*)d_in[7];
    float* out = (float*)d_out;

    float* XL; cudaGetSymbolAddress((void**)&XL, g_XL);
    float* XR; cudaGetSymbolAddress((void**)&XR, g_XR);

    zero_cnt_kernel<<<(NN + 255) / 256, 256>>>();

    int gemm_blocks = (NN + BM - 1) / BM;
    gemm_kernel<<<gemm_blocks, 256>>>(x, W_l, b_l, XL);
    gemm_kernel<<<gemm_blocks, 256>>>(x, W_r, b_r, XR);

    hist_kernel<<<(NE + 255) / 256, 256>>>(ei);
    scan1_kernel<<<NBLK, SCAN_B>>>();
    scan2_kernel<<<1, 32>>>();
    scan3_kernel<<<(NN + 255) / 256, 256>>>();
    scatter_kernel<<<(NE + 255) / 256, 256>>>(ei);

    fused_kernel<<<(NN * 32 + 255) / 256, 256>>>(x, att, bias, out);
}

// round 7
// speedup vs baseline: 2.5511x; 1.2011x over previous
#include <cuda_runtime.h>

#define NN 50000
#define NE 800000
#define H  6
#define C  32
#define D  192
#define NEG_SLOPE 0.2f
#define LOG2E 1.4426950408889634f

#define SCAN_B 512
#define NBLK ((NN + SCAN_B - 1) / SCAN_B)   // 98

// ---------------- static scratch ----------------
__device__ float g_XL[NN * D];   // x @ W_l^T + b_l
__device__ float g_XR[NN * D];   // x @ W_r^T + b_r
__device__ int   g_CNT[NN];      // in-degree (excl self loop)
__device__ int   g_ROW[NN];      // exclusive rowptr
__device__ int   g_CUR[NN];      // scatter cursor
__device__ int   g_BT[NBLK];     // scan block totals
__device__ int   g_ESRC[NE];     // CSR: src ids grouped by dst

// ---------------- packed f32x2 helpers (Blackwell FFMA2) ------------------
#define PACK2(o, lo, hi) asm("mov.b64 %0, {%1, %2};" : "=l"(o) : "f"(lo), "f"(hi))
#define UNPACK2(lo, hi, i) asm("mov.b64 {%0, %1}, %2;" : "=f"(lo), "=f"(hi) : "l"(i))
#define FMA2(d, a, b, c) asm("fma.rn.f32x2 %0, %1, %2, %3;" : "=l"(d) : "l"(a), "l"(b), "l"(c))

// ---------------- GEMM: out[n][d] = sum_k X[n][k]*W[d][k] + b[d] ----------
#define BM 64
__global__ __launch_bounds__(256) void gemm_kernel(const float* __restrict__ X,
                                                   const float* __restrict__ W,
                                                   const float* __restrict__ b,
                                                   float* __restrict__ out) {
    __shared__ float xs[BM][33];
    __shared__ float ws[32][196];
    const int tid = threadIdx.x;
    const int tx = tid & 31, ty = tid >> 5;
    const int row0 = blockIdx.x * BM;

    unsigned long long acc[8][3];
#pragma unroll
    for (int i = 0; i < 8; i++)
#pragma unroll
        for (int j = 0; j < 3; j++) acc[i][j] = 0ull;

    for (int kt = 0; kt < 6; kt++) {
        const int k0 = kt * 32;
        {
            const int kk = tid & 31;
            for (int r = tid >> 5; r < BM; r += 8) {
                int row = row0 + r;
                xs[r][kk] = (row < NN) ? X[(size_t)row * D + k0 + kk] : 0.f;
            }
        }
        {
            const int kk = tid & 31;
            for (int d = tid >> 5; d < D; d += 8)
                ws[kk][d] = W[(size_t)d * D + k0 + kk];
        }
        __syncthreads();
#pragma unroll
        for (int k = 0; k < 32; k++) {
            float2 wa = *(const float2*)&ws[k][tx * 4];
            float2 wb = *(const float2*)&ws[k][tx * 4 + 2];
            float2 wc = *(const float2*)&ws[k][128 + tx * 2];
            unsigned long long wA, wB, wC;
            PACK2(wA, wa.x, wa.y);
            PACK2(wB, wb.x, wb.y);
            PACK2(wC, wc.x, wc.y);
#pragma unroll
            for (int i = 0; i < 8; i++) {
                float xv = xs[ty * 8 + i][k];
                unsigned long long xp;
                PACK2(xp, xv, xv);
                FMA2(acc[i][0], xp, wA, acc[i][0]);
                FMA2(acc[i][1], xp, wB, acc[i][1]);
                FMA2(acc[i][2], xp, wC, acc[i][2]);
            }
        }
        __syncthreads();
    }

    float4 bb0 = *(const float4*)&b[tx * 4];
    float2 bb1 = *(const float2*)&b[128 + tx * 2];
#pragma unroll
    for (int i = 0; i < 8; i++) {
        int row = row0 + ty * 8 + i;
        if (row < NN) {
            float a0, a1, a2, a3, a4, a5;
            UNPACK2(a0, a1, acc[i][0]);
            UNPACK2(a2, a3, acc[i][1]);
            UNPACK2(a4, a5, acc[i][2]);
            float4 o0 = {a0 + bb0.x, a1 + bb0.y, a2 + bb0.z, a3 + bb0.w};
            *(float4*)&out[(size_t)row * D + tx * 4] = o0;
            float2 o1 = {a4 + bb1.x, a5 + bb1.y};
            *(float2*)&out[(size_t)row * D + 128 + tx * 2] = o1;
        }
    }
}

// ---------------- CSR build ----------------
__global__ void zero_cnt_kernel() {
    int i = blockIdx.x * blockDim.x + threadIdx.x;
    if (i < NN) g_CNT[i] = 0;
}

__global__ void hist_kernel(const int* __restrict__ ei) {
    int e = blockIdx.x * blockDim.x + threadIdx.x;
    if (e < NE) atomicAdd(&g_CNT[ei[NE + e]], 1);
}

__global__ void scan1_kernel() {
    __shared__ int s[SCAN_B];
    int i = blockIdx.x * SCAN_B + threadIdx.x;
    int v = (i < NN) ? g_CNT[i] : 0;
    s[threadIdx.x] = v;
    __syncthreads();
    for (int off = 1; off < SCAN_B; off <<= 1) {
        int t = (threadIdx.x >= off) ? s[threadIdx.x - off] : 0;
        __syncthreads();
        s[threadIdx.x] += t;
        __syncthreads();
    }
    if (i < NN) g_ROW[i] = s[threadIdx.x] - v;
    if (threadIdx.x == SCAN_B - 1) g_BT[blockIdx.x] = s[threadIdx.x];
}

__global__ void scan2_kernel() {
    if (threadIdx.x == 0) {
        int acc = 0;
        for (int b = 0; b < NBLK; b++) { int t = g_BT[b]; g_BT[b] = acc; acc += t; }
    }
}

__global__ void scan3_kernel() {
    int i = blockIdx.x * blockDim.x + threadIdx.x;
    if (i < NN) {
        int r = g_ROW[i] + g_BT[i / SCAN_B];
        g_ROW[i] = r;
        g_CUR[i] = r;
    }
}

__global__ void scatter_kernel(const int* __restrict__ ei) {
    int e = blockIdx.x * blockDim.x + threadIdx.x;
    if (e < NE) {
        int dst = ei[NE + e];
        int pos = atomicAdd(&g_CUR[dst], 1);
        g_ESRC[pos] = ei[e];
    }
}

// ---------------- fast exp2 ----------------
__device__ __forceinline__ float ex2(float v) {
    float r;
    asm("ex2.approx.f32 %0, %1;" : "=f"(r) : "f"(v));
    return r;
}

// ---------------- fused GATv2 ----------------
// one warp per dst. Lane l owns:
//   part A: channels 4l..4l+3  (head l>>3, heads 0-3)   -> float4
//   part B: channels 128+2l..+1 (head 4+(l>>4), heads 4-5) -> float2
// Head sums: A = 8-lane groups (xor 4,2,1); B = 16-lane groups (xor 8,4,2,1).
// exp result is per-lane-local (own head) -> no broadcasts needed.
__global__ void fused_kernel(const float* __restrict__ x,
                             const float* __restrict__ att,
                             const float* __restrict__ bias,
                             float* __restrict__ out) {
    const int dst = (blockIdx.x * blockDim.x + threadIdx.x) >> 5;
    const int lane = threadIdx.x & 31;
    if (dst >= NN) return;

    const int offA = lane * 4;          // channels 4l..4l+3
    const int offB = 128 + lane * 2;    // channels 128+2l..+1

    const float4 xrA = *(const float4*)&g_XR[(size_t)dst * D + offA];
    const float2 xrB = *(const float2*)&g_XR[(size_t)dst * D + offB];
    float4 aA = *(const float4*)&att[offA];
    float2 aB = *(const float2*)&att[offB];
    aA.x *= LOG2E; aA.y *= LOG2E; aA.z *= LOG2E; aA.w *= LOG2E;
    aB.x *= LOG2E; aB.y *= LOG2E;

    float4 accA = {0.f, 0.f, 0.f, 0.f};
    float2 accB = {0.f, 0.f};
    float denA = 0.f, denB = 0.f;

#define EDGE_BODY(src)                                                          \
    {                                                                           \
        const float* xlp = g_XL + (size_t)(src) * D;                            \
        float4 xlA = *(const float4*)&xlp[offA];                                \
        float2 xlB = *(const float2*)&xlp[offB];                                \
        float m0 = xlA.x + xrA.x, m1 = xlA.y + xrA.y;                           \
        float m2 = xlA.z + xrA.z, m3 = xlA.w + xrA.w;                           \
        float tA = fmaxf(m0, NEG_SLOPE * m0) * aA.x;                            \
        tA = fmaf(fmaxf(m1, NEG_SLOPE * m1), aA.y, tA);                         \
        tA = fmaf(fmaxf(m2, NEG_SLOPE * m2), aA.z, tA);                         \
        tA = fmaf(fmaxf(m3, NEG_SLOPE * m3), aA.w, tA);                         \
        float n0 = xlB.x + xrB.x, n1 = xlB.y + xrB.y;                           \
        float tB = fmaxf(n0, NEG_SLOPE * n0) * aB.x;                            \
        tB = fmaf(fmaxf(n1, NEG_SLOPE * n1), aB.y, tB);                         \
        tA += __shfl_xor_sync(0xffffffffu, tA, 4);                              \
        tB += __shfl_xor_sync(0xffffffffu, tB, 8);                              \
        tA += __shfl_xor_sync(0xffffffffu, tA, 2);                              \
        tB += __shfl_xor_sync(0xffffffffu, tB, 4);                              \
        tA += __shfl_xor_sync(0xffffffffu, tA, 1);                              \
        tB += __shfl_xor_sync(0xffffffffu, tB, 2);                              \
        tB += __shfl_xor_sync(0xffffffffu, tB, 1);                              \
        float eA = ex2(tA);                                                     \
        float eB = ex2(tB);                                                     \
        denA += eA; denB += eB;                                                 \
        accA.x = fmaf(eA, xlA.x, accA.x);                                       \
        accA.y = fmaf(eA, xlA.y, accA.y);                                       \
        accA.z = fmaf(eA, xlA.z, accA.z);                                       \
        accA.w = fmaf(eA, xlA.w, accA.w);                                       \
        accB.x = fmaf(eB, xlB.x, accB.x);                                       \
        accB.y = fmaf(eB, xlB.y, accB.y);                                       \
    }

    // self-loop seed
    EDGE_BODY(dst)

    const int jb = g_ROW[dst];
    const int je = jb + g_CNT[dst];
    int j = jb;
    for (; j + 1 < je; j += 2) {
        int s0 = g_ESRC[j], s1 = g_ESRC[j + 1];
        EDGE_BODY(s0)
        EDGE_BODY(s1)
    }
    if (j < je) {
        int s0 = g_ESRC[j];
        EDGE_BODY(s0)
    }
#undef EDGE_BODY

    const float rdA = 1.f / (denA + 1e-16f);
    const float rdB = 1.f / (denB + 1e-16f);
    const float4 xpA = *(const float4*)&x[(size_t)dst * D + offA];
    const float2 xpB = *(const float2*)&x[(size_t)dst * D + offB];
    const float4 bA = *(const float4*)&bias[offA];
    const float2 bB = *(const float2*)&bias[offB];
    float4 oA;
    oA.x = fmaxf(xpA.x + accA.x * rdA + bA.x, 0.f);
    oA.y = fmaxf(xpA.y + accA.y * rdA + bA.y, 0.f);
    oA.z = fmaxf(xpA.z + accA.z * rdA + bA.z, 0.f);
    oA.w = fmaxf(xpA.w + accA.w * rdA + bA.w, 0.f);
    float2 oB;
    oB.x = fmaxf(xpB.x + accB.x * rdB + bB.x, 0.f);
    oB.y = fmaxf(xpB.y + accB.y * rdB + bB.y, 0.f);
    *(float4*)&out[(size_t)dst * D + offA] = oA;
    *(float2*)&out[(size_t)dst * D + offB] = oB;
}

// ---------------- launch --------------------------------------------------
extern "C" void kernel_launch(void* const* d_in, const int* in_sizes, int n_in,
                              void* d_out, int out_size) {
    const float* x    = (const float*)d_in[0];
    const float* W_l  = (const float*)d_in[1];
    const float* b_l  = (const float*)d_in[2];
    const float* W_r  = (const float*)d_in[3];
    const float* b_r  = (const float*)d_in[4];
    const float* att  = (const float*)d_in[5];
    const float* bias = (const float*)d_in[6];
    const int*   ei   = (const int*)d_in[7];
    float* out = (float*)d_out;

    float* XL; cudaGetSymbolAddress((void**)&XL, g_XL);
    float* XR; cudaGetSymbolAddress((void**)&XR, g_XR);

    zero_cnt_kernel<<<(NN + 255) / 256, 256>>>();

    int gemm_blocks = (NN + BM - 1) / BM;
    gemm_kernel<<<gemm_blocks, 256>>>(x, W_l, b_l, XL);
    gemm_kernel<<<gemm_blocks, 256>>>(x, W_r, b_r, XR);

    hist_kernel<<<(NE + 255) / 256, 256>>>(ei);
    scan1_kernel<<<NBLK, SCAN_B>>>();
    scan2_kernel<<<1, 32>>>();
    scan3_kernel<<<(NN + 255) / 256, 256>>>();
    scatter_kernel<<<(NE + 255) / 256, 256>>>(ei);

    fused_kernel<<<(NN * 32 + 255) / 256, 256>>>(x, att, bias, out);
}